// round 1
// baseline (speedup 1.0000x reference)
#include <cuda_runtime.h>

#define EPSV 1e-5f

// ---------------- scratch (device globals; no allocation allowed) ----------------
__device__ float g_part[2][4 * 64 * 1024];   // split-K partial conv outputs (2 x 1MB)
__device__ float g_y[4 * 64 * 1024];         // combined raw conv output (pre-BN)
__device__ float g_bn_a[64];                 // folded BN scale
__device__ float g_bn_b[64];                 // folded BN shift
__device__ float g_xf[4 * 12 * 1024];        // regressor output (N,T,WH)
__device__ float g_wT[161280];               // transposed weights [ci][tap][co] per layer

// wT layout offsets:
//  L0:    [12][9][64]  at 0        (6912)
//  L1..4: [64][9][64]  at 6912 + l*36864
//  reg:   [64][9][12]  at 154368   (6912)

// ---------------- weight transpose ----------------
__global__ void wtrans_kernel(const float* __restrict__ conv0_w,
                              const float* __restrict__ conv_w,
                              const float* __restrict__ reg_w) {
    int i = blockIdx.x * 256 + threadIdx.x;
    if (i < 6912) {
        // dst [ci][tap][co64]
        int co = i & 63;
        int rest = i >> 6;
        int tap = rest % 9, ci = rest / 9;
        g_wT[i] = conv0_w[co * 108 + ci * 9 + tap];
        return;
    }
    int j = i - 6912;
    if (j >= 0 && j < 4 * 36864) {
        int l = j / 36864, k = j % 36864;
        int co = k & 63;
        int rest = k >> 6;
        int tap = rest % 9, ci = rest / 9;
        g_wT[i] = conv_w[(l * 64 + co) * 576 + ci * 9 + tap];
        return;
    }
    int r = i - 154368;
    if (r >= 0 && r < 6912) {
        int co = r % 12;
        int rest = r / 12;
        int tap = rest % 9, ci = rest / 9;
        g_wT[i] = reg_w[co * 576 + ci * 9 + tap];
    }
}

// ---------------- conv3x3 SAME, split-K over ci (gridDim.y = 2) ----------------
// in:  [4][CI][32][32]  (raw; if BN: apply relu(a*v+b) on load)
// wT:  [CI][9][CO]
// part: two halves at stride 4*64*1024 (capacity stride), raw partial sums
template <int CI, int CO, bool BN>
__global__ __launch_bounds__(256) void conv_kernel(const float* __restrict__ in,
                                                   const float* __restrict__ wT,
                                                   float* __restrict__ part) {
    constexpr int TCO = CO / 4;   // co-quads
    constexpr int CICH = 8;
    const int tid = threadIdx.x;
    const int px0 = blockIdx.x * 64;        // 64 px = 2 rows x 32 cols of one image
    const int n = px0 >> 10;
    const int r0 = (px0 & 1023) >> 5;
    const int ciHalf = CI / 2;
    const int ci0 = blockIdx.y * ciHalf;

    __shared__ float smA[CICH][4][36];      // input tile: rows r0-1..r0+2, cols -1..32 at [col+1]
    __shared__ float smW[CICH][9][CO];      // weights, co-contiguous

    const int tpx = tid / TCO;              // 0..15 valid
    const int tco = tid % TCO;
    const bool active = (tpx < 16);
    const int pr = tpx >> 3;                // output row within tile (0/1)
    const int pc = (tpx & 7) * 4;           // output col base

    float acc[4][4];
#pragma unroll
    for (int a = 0; a < 4; a++)
#pragma unroll
        for (int b = 0; b < 4; b++) acc[a][b] = 0.f;

    for (int cc = 0; cc < ciHalf; cc += CICH) {
        const int cn = min(CICH, ciHalf - cc);
        __syncthreads();
        // stage input (with BN+ReLU folded on load)
        for (int idx = tid; idx < cn * 136; idx += 256) {
            int ci = idx / 136;
            int rem = idx % 136;
            int row = rem / 34, col = rem % 34;
            int gr = r0 - 1 + row, gc = col - 1;
            int cig = ci0 + cc + ci;
            float v = 0.f;
            if ((unsigned)gr < 32u && (unsigned)gc < 32u) {
                v = in[((n * CI + cig) << 10) + (gr << 5) + gc];
                if (BN) v = fmaxf(fmaf(v, g_bn_a[cig], g_bn_b[cig]), 0.f);
            }
            smA[ci][row][col] = v;
        }
        // stage weights (flat contiguous copy)
        {
            const float* src = wT + (ci0 + cc) * 9 * CO;
            float* dstw = &smW[0][0][0];
            for (int idx = tid; idx < cn * 9 * CO; idx += 256) dstw[idx] = src[idx];
        }
        __syncthreads();

        if (active) {
            for (int ci = 0; ci < cn; ci++) {
#pragma unroll
                for (int kh = 0; kh < 3; kh++) {
                    float xv[6];
#pragma unroll
                    for (int j = 0; j < 6; j++) xv[j] = smA[ci][pr + kh][pc + j];
#pragma unroll
                    for (int kw = 0; kw < 3; kw++) {
                        const float4 wv = *(const float4*)&smW[ci][kh * 3 + kw][tco * 4];
#pragma unroll
                        for (int jp = 0; jp < 4; jp++) {
                            float xx = xv[kw + jp];
                            acc[jp][0] = fmaf(xx, wv.x, acc[jp][0]);
                            acc[jp][1] = fmaf(xx, wv.y, acc[jp][1]);
                            acc[jp][2] = fmaf(xx, wv.z, acc[jp][2]);
                            acc[jp][3] = fmaf(xx, wv.w, acc[jp][3]);
                        }
                    }
                }
            }
        }
    }

    if (active) {
        float* dst = part + blockIdx.y * (4 * 64 * 1024);
#pragma unroll
        for (int jc = 0; jc < 4; jc++) {
            int co = tco * 4 + jc;
            float4 v = make_float4(acc[0][jc], acc[1][jc], acc[2][jc], acc[3][jc]);
            *(float4*)&dst[((n * CO + co) << 10) + ((r0 + pr) << 5) + pc] = v;
        }
    }
}

// ---------------- combine split halves + BN training stats -> folded (a,b) ----------------
__global__ void stats_kernel(const float* __restrict__ gamma, const float* __restrict__ beta) {
    const int c = blockIdx.x;        // channel 0..63
    const int tid = threadIdx.x;     // 256
    float s = 0.f, ss = 0.f;
    for (int k = tid; k < 4096; k += 256) {
        int n = k >> 10, p = k & 1023;
        int idx = ((n * 64 + c) << 10) + p;
        float y = g_part[0][idx] + g_part[1][idx];
        g_y[idx] = y;
        s += y;
        ss += y * y;
    }
    __shared__ float shs[256], shq[256];
    shs[tid] = s;
    shq[tid] = ss;
    __syncthreads();
    for (int o = 128; o > 0; o >>= 1) {
        if (tid < o) {
            shs[tid] += shs[tid + o];
            shq[tid] += shq[tid + o];
        }
        __syncthreads();
    }
    if (tid == 0) {
        float mean = shs[0] * (1.f / 4096.f);
        float var = shq[0] * (1.f / 4096.f) - mean * mean;
        float a = gamma[c] * rsqrtf(var + EPSV);
        g_bn_a[c] = a;
        g_bn_b[c] = beta[c] - mean * a;
    }
}

// ---------------- combine regressor halves + bias -> xf ----------------
__global__ void combine_xf_kernel(const float* __restrict__ reg_b) {
    int i = blockIdx.x * 256 + threadIdx.x;
    if (i < 4 * 12 * 1024) {
        int c = (i >> 10) % 12;
        g_xf[i] = g_part[0][i] + g_part[1][i] + reg_b[c];
    }
}

// ---------------- attention: per row (n,t,i): softmax(att_w[t,i,:]*xf[n,t,:]) ----------------
__global__ __launch_bounds__(256) void attention_kernel(const float* __restrict__ att_w,
                                                         float* __restrict__ out,
                                                         float* __restrict__ att) {
    const int rid = blockIdx.x;          // n*12*1024 + t*1024 + i
    const int i = rid & 1023;
    const int nt = rid >> 10;            // n*12 + t
    const int t = nt % 12;
    const int tid = threadIdx.x;
    const int lane = tid & 31, warp = tid >> 5;

    const float4* wrow = (const float4*)(att_w + (((size_t)(t << 10) + i) << 10));
    const float4* xrow = (const float4*)(g_xf + ((size_t)nt << 10));

    float4 w = __ldg(wrow + tid);
    float4 x = __ldg(xrow + tid);
    float s0 = w.x * x.x, s1 = w.y * x.y, s2 = w.z * x.z, s3 = w.w * x.w;

    // --- block max ---
    float m = fmaxf(fmaxf(s0, s1), fmaxf(s2, s3));
#pragma unroll
    for (int o = 16; o > 0; o >>= 1) m = fmaxf(m, __shfl_xor_sync(0xffffffffu, m, o));
    __shared__ float shA[8];
    __shared__ float shS[8], shD[8];
    if (lane == 0) shA[warp] = m;
    __syncthreads();
    m = shA[0];
#pragma unroll
    for (int k = 1; k < 8; k++) m = fmaxf(m, shA[k]);

    // --- exp + sums ---
    float e0 = __expf(s0 - m), e1 = __expf(s1 - m), e2 = __expf(s2 - m), e3 = __expf(s3 - m);
    float es = e0 + e1 + e2 + e3;
    float ed = e0 * x.x + e1 * x.y + e2 * x.z + e3 * x.w;
#pragma unroll
    for (int o = 16; o > 0; o >>= 1) {
        es += __shfl_xor_sync(0xffffffffu, es, o);
        ed += __shfl_xor_sync(0xffffffffu, ed, o);
    }
    if (lane == 0) { shS[warp] = es; shD[warp] = ed; }
    __syncthreads();
    float tes = shS[0], ted = shD[0];
#pragma unroll
    for (int k = 1; k < 8; k++) { tes += shS[k]; ted += shD[k]; }

    float inv = __frcp_rn(tes);
    float4 o4 = make_float4(e0 * inv, e1 * inv, e2 * inv, e3 * inv);
    ((float4*)(att + ((size_t)rid << 10)))[tid] = o4;
    if (tid == 0) out[rid] = ted * inv;
}

// ---------------- launcher ----------------
extern "C" void kernel_launch(void* const* d_in, const int* in_sizes, int n_in,
                              void* d_out, int out_size) {
    (void)in_sizes; (void)n_in; (void)out_size;
    const float* x        = (const float*)d_in[0];
    const float* conv0_w  = (const float*)d_in[1];
    const float* conv_w   = (const float*)d_in[2];
    // d_in[3] = conv_b: exactly cancelled by BN (and zero) -> unused
    const float* bn_gamma = (const float*)d_in[4];
    const float* bn_beta  = (const float*)d_in[5];
    const float* reg_w    = (const float*)d_in[6];
    const float* reg_b    = (const float*)d_in[7];
    const float* att_w    = (const float*)d_in[8];
    float* out = (float*)d_out;

    float *p_y, *p_part, *p_wT;
    cudaGetSymbolAddress((void**)&p_y, g_y);
    cudaGetSymbolAddress((void**)&p_part, g_part);
    cudaGetSymbolAddress((void**)&p_wT, g_wT);

    wtrans_kernel<<<630, 256>>>(conv0_w, conv_w, reg_w);

    // layer 0: 12 -> 64, no BN on input
    conv_kernel<12, 64, false><<<dim3(64, 2), 256>>>(x, p_wT, p_part);
    stats_kernel<<<64, 256>>>(bn_gamma + 0, bn_beta + 0);

    // layers 1..4: 64 -> 64, BN+ReLU folded into input load
    conv_kernel<64, 64, true><<<dim3(64, 2), 256>>>(p_y, p_wT + 6912 + 0 * 36864, p_part);
    stats_kernel<<<64, 256>>>(bn_gamma + 1 * 64, bn_beta + 1 * 64);
    conv_kernel<64, 64, true><<<dim3(64, 2), 256>>>(p_y, p_wT + 6912 + 1 * 36864, p_part);
    stats_kernel<<<64, 256>>>(bn_gamma + 2 * 64, bn_beta + 2 * 64);
    conv_kernel<64, 64, true><<<dim3(64, 2), 256>>>(p_y, p_wT + 6912 + 2 * 36864, p_part);
    stats_kernel<<<64, 256>>>(bn_gamma + 3 * 64, bn_beta + 3 * 64);
    conv_kernel<64, 64, true><<<dim3(64, 2), 256>>>(p_y, p_wT + 6912 + 3 * 36864, p_part);
    stats_kernel<<<64, 256>>>(bn_gamma + 4 * 64, bn_beta + 4 * 64);

    // regressor: 64 -> 12 (BN4+ReLU on input), then combine + bias
    conv_kernel<64, 12, true><<<dim3(64, 2), 256>>>(p_y, p_wT + 154368, p_part);
    combine_xf_kernel<<<192, 256>>>(reg_b);

    // attention: out (49152 floats) then att (4*12*1024*1024 floats)
    attention_kernel<<<49152, 256>>>(att_w, out, out + 49152);
}

// round 2
// speedup vs baseline: 1.3357x; 1.3357x over previous
#include <cuda_runtime.h>

typedef unsigned long long ull;
#define EPSV 1e-5f

// ---------------- scratch (device globals) ----------------
__device__ float g_part[4][4 * 64 * 1024];   // split-K(4) partial conv outputs
__device__ float g_y[4 * 64 * 1024];         // combined raw conv output (pre-BN)
__device__ float g_bn_a[64];                 // folded BN scale
__device__ float g_bn_b[64];                 // folded BN shift
__device__ float g_xf[4 * 12 * 1024];        // regressor output (N,T,WH)
__device__ float g_wT[163584];               // transposed weights [ci][tap][co]
__device__ float2 g_red[64][4];              // per-(channel, image) {sum, sumsq}
__device__ int g_cnt[5 * 64];                // last-block counters per layer/channel

// wT layout: L0 [12][9][64] @0 (6912); L1..4 [64][9][64] @6912+l*36864; reg [64][9][16] @154368 (9216, co padded 12->16)

__device__ __forceinline__ void fma2(ull& acc, ull x, ull w) {
    asm("fma.rn.f32x2 %0, %1, %2, %0;" : "+l"(acc) : "l"(x), "l"(w));
}

// ---------------- weight transpose + counter reset ----------------
__global__ void wtrans_kernel(const float* __restrict__ conv0_w,
                              const float* __restrict__ conv_w,
                              const float* __restrict__ reg_w) {
    int i = blockIdx.x * 256 + threadIdx.x;
    if (i < 320) g_cnt[i] = 0;
    if (i < 6912) {
        int co = i & 63, rest = i >> 6;
        int tap = rest % 9, ci = rest / 9;
        g_wT[i] = conv0_w[co * 108 + ci * 9 + tap];
        return;
    }
    int j = i - 6912;
    if (j >= 0 && j < 147456) {
        int l = j / 36864, k = j % 36864;
        int co = k & 63, rest = k >> 6;
        int tap = rest % 9, ci = rest / 9;
        g_wT[i] = conv_w[(l * 64 + co) * 576 + ci * 9 + tap];
        return;
    }
    int r = i - 154368;
    if (r >= 0 && r < 9216) {
        int co = r & 15, rest = r >> 4;
        int tap = rest % 9, ci = rest / 9;
        g_wT[i] = (co < 12) ? reg_w[co * 576 + ci * 9 + tap] : 0.f;
    }
}

// ---------------- conv3x3 SAME, split-K x4, packed f32x2 FMA ----------------
// in:  [4][CI][32][32] raw; if BN: relu(a*v+b) applied on SMEM stage
// wT:  [CI][9][CO] (CO possibly padded)
// part: 4 quarters at stride 4*64*1024, raw partial sums, layout [n][STORECO][1024]
template <int CI, int CO, int ROWS, bool BN, int STORECO>
__global__ __launch_bounds__(256) void conv2_kernel(const float* __restrict__ in,
                                                    const float* __restrict__ wT,
                                                    float* __restrict__ part) {
    constexpr int TCO = CO / 4;               // co-quads
    constexpr int CIQ = CI / 4;               // ci per block (K quarter)
    constexpr int CICH = (CIQ < 8) ? CIQ : 8; // ci chunk staged in smem
    const int tid = threadIdx.x;
    const int tco = tid % TCO;
    const int tpx = tid / TCO;                // px-quad index
    const int pr = tpx >> 3;                  // row within tile
    const int pc = (tpx & 7) * 4;             // col base
    const int px0 = blockIdx.x * (ROWS * 32);
    const int n = px0 >> 10;
    const int r0 = (px0 & 1023) >> 5;
    const int ci0 = blockIdx.y * CIQ;

    __shared__ __align__(16) float2 smA[CICH][ROWS + 2][36];  // duplicated pixels (f32x2 operand)
    __shared__ __align__(16) float smW[CICH][9][CO];

    ull acc[4][2];
#pragma unroll
    for (int a = 0; a < 4; a++) { acc[a][0] = 0ULL; acc[a][1] = 0ULL; }

#pragma unroll 1
    for (int cc = 0; cc < CIQ; cc += CICH) {
        __syncthreads();
        // stage input (BN+ReLU folded), duplicated for packed FMA
        for (int idx = tid; idx < CICH * (ROWS + 2) * 36; idx += 256) {
            int ci = idx / ((ROWS + 2) * 36);
            int rem = idx % ((ROWS + 2) * 36);
            int row = rem / 36, col = rem % 36;
            int gr = r0 - 1 + row, gc = col - 1;
            int cig = ci0 + cc + ci;
            float v = 0.f;
            if ((unsigned)gr < 32u && (unsigned)gc < 32u) {
                v = in[((n * CI + cig) << 10) + (gr << 5) + gc];
                if (BN) v = fmaxf(fmaf(v, g_bn_a[cig], g_bn_b[cig]), 0.f);
            }
            smA[ci][row][col] = make_float2(v, v);
        }
        // stage weights (contiguous float4 copy)
        {
            const float4* src = (const float4*)(wT + (ci0 + cc) * 9 * CO);
            float4* dstw = (float4*)&smW[0][0][0];
            for (int idx = tid; idx < CICH * 9 * CO / 4; idx += 256) dstw[idx] = src[idx];
        }
        __syncthreads();

#pragma unroll
        for (int ci = 0; ci < CICH; ci++) {
#pragma unroll
            for (int kh = 0; kh < 3; kh++) {
                ull xp[6];
#pragma unroll
                for (int j = 0; j < 6; j++) xp[j] = *(const ull*)&smA[ci][pr + kh][pc + j];
#pragma unroll
                for (int kw = 0; kw < 3; kw++) {
                    ulonglong2 wv = *(const ulonglong2*)&smW[ci][kh * 3 + kw][tco * 4];
#pragma unroll
                    for (int jp = 0; jp < 4; jp++) {
                        fma2(acc[jp][0], xp[kw + jp], wv.x);
                        fma2(acc[jp][1], xp[kw + jp], wv.y);
                    }
                }
            }
        }
    }

    // epilogue: unpack pairs, store co-major float4 over 4 px
    union U { ull u; float2 f; };
    float vals[4][4];
#pragma unroll
    for (int jp = 0; jp < 4; jp++) {
        U u0, u1; u0.u = acc[jp][0]; u1.u = acc[jp][1];
        vals[jp][0] = u0.f.x; vals[jp][1] = u0.f.y;
        vals[jp][2] = u1.f.x; vals[jp][3] = u1.f.y;
    }
    float* dst = part + blockIdx.y * (4 * 64 * 1024);
#pragma unroll
    for (int jc = 0; jc < 4; jc++) {
        int co = tco * 4 + jc;
        if (STORECO == CO || co < STORECO) {
            float4 o = make_float4(vals[0][jc], vals[1][jc], vals[2][jc], vals[3][jc]);
            *(float4*)&dst[((n * STORECO + co) << 10) + ((r0 + pr) << 5) + pc] = o;
        }
    }
}

// ---------------- combine 4 partials -> y, BN stats, last-block folds (a,b) ----------------
__global__ __launch_bounds__(256) void stats_kernel(const float* __restrict__ gamma,
                                                    const float* __restrict__ beta,
                                                    int layer) {
    const int b = blockIdx.x;
    const int c = b & 63;        // channel
    const int n = b >> 6;        // image
    const int tid = threadIdx.x;
    const int base = ((n * 64 + c) << 10) + tid * 4;

    float4 p0 = *(const float4*)&g_part[0][base];
    float4 p1 = *(const float4*)&g_part[1][base];
    float4 p2 = *(const float4*)&g_part[2][base];
    float4 p3 = *(const float4*)&g_part[3][base];
    float4 y = make_float4(p0.x + p1.x + p2.x + p3.x, p0.y + p1.y + p2.y + p3.y,
                           p0.z + p1.z + p2.z + p3.z, p0.w + p1.w + p2.w + p3.w);
    *(float4*)&g_y[base] = y;
    float s = y.x + y.y + y.z + y.w;
    float ss = y.x * y.x + y.y * y.y + y.z * y.z + y.w * y.w;

    const int lane = tid & 31, warp = tid >> 5;
#pragma unroll
    for (int o = 16; o > 0; o >>= 1) {
        s += __shfl_xor_sync(0xffffffffu, s, o);
        ss += __shfl_xor_sync(0xffffffffu, ss, o);
    }
    __shared__ float shs[8], shq[8];
    if (lane == 0) { shs[warp] = s; shq[warp] = ss; }
    __syncthreads();
    if (tid == 0) {
        float S = 0.f, Q = 0.f;
#pragma unroll
        for (int k = 0; k < 8; k++) { S += shs[k]; Q += shq[k]; }
        g_red[c][n] = make_float2(S, Q);
        __threadfence();
        int old = atomicAdd(&g_cnt[layer * 64 + c], 1);
        if (old == 3) {
            __threadfence();
            volatile float* rp = (volatile float*)&g_red[c][0];
            float TS = 0.f, TQ = 0.f;
#pragma unroll
            for (int k = 0; k < 4; k++) { TS += rp[2 * k]; TQ += rp[2 * k + 1]; }
            float mean = TS * (1.f / 4096.f);
            float var = TQ * (1.f / 4096.f) - mean * mean;
            float a = gamma[c] * rsqrtf(var + EPSV);
            g_bn_a[c] = a;
            g_bn_b[c] = beta[c] - mean * a;
        }
    }
}

// ---------------- combine regressor partials + bias -> xf ----------------
__global__ void combine_xf_kernel(const float* __restrict__ reg_b) {
    int i = blockIdx.x * 256 + threadIdx.x;
    if (i < 4 * 12 * 1024) {
        int c = (i >> 10) % 12;
        g_xf[i] = g_part[0][i] + g_part[1][i] + g_part[2][i] + g_part[3][i] + reg_b[c];
    }
}

// ---------------- attention ----------------
__global__ __launch_bounds__(256) void attention_kernel(const float* __restrict__ att_w,
                                                        float* __restrict__ out,
                                                        float* __restrict__ att) {
    const int rid = blockIdx.x;          // n*12*1024 + t*1024 + i
    const int i = rid & 1023;
    const int nt = rid >> 10;
    const int t = nt % 12;
    const int tid = threadIdx.x;
    const int lane = tid & 31, warp = tid >> 5;

    const float4* wrow = (const float4*)(att_w + (((size_t)(t << 10) + i) << 10));
    const float4* xrow = (const float4*)(g_xf + ((size_t)nt << 10));

    float4 w = __ldg(wrow + tid);
    float4 x = __ldg(xrow + tid);
    float s0 = w.x * x.x, s1 = w.y * x.y, s2 = w.z * x.z, s3 = w.w * x.w;

    float m = fmaxf(fmaxf(s0, s1), fmaxf(s2, s3));
#pragma unroll
    for (int o = 16; o > 0; o >>= 1) m = fmaxf(m, __shfl_xor_sync(0xffffffffu, m, o));
    __shared__ float shA[8], shS[8], shD[8];
    if (lane == 0) shA[warp] = m;
    __syncthreads();
    m = shA[0];
#pragma unroll
    for (int k = 1; k < 8; k++) m = fmaxf(m, shA[k]);

    float e0 = __expf(s0 - m), e1 = __expf(s1 - m), e2 = __expf(s2 - m), e3 = __expf(s3 - m);
    float es = e0 + e1 + e2 + e3;
    float ed = e0 * x.x + e1 * x.y + e2 * x.z + e3 * x.w;
#pragma unroll
    for (int o = 16; o > 0; o >>= 1) {
        es += __shfl_xor_sync(0xffffffffu, es, o);
        ed += __shfl_xor_sync(0xffffffffu, ed, o);
    }
    if (lane == 0) { shS[warp] = es; shD[warp] = ed; }
    __syncthreads();
    float tes = shS[0], ted = shD[0];
#pragma unroll
    for (int k = 1; k < 8; k++) { tes += shS[k]; ted += shD[k]; }

    float inv = __frcp_rn(tes);
    float4 o4 = make_float4(e0 * inv, e1 * inv, e2 * inv, e3 * inv);
    __stcs(((float4*)(att + ((size_t)rid << 10))) + tid, o4);
    if (tid == 0) out[rid] = ted * inv;
}

// ---------------- launcher ----------------
extern "C" void kernel_launch(void* const* d_in, const int* in_sizes, int n_in,
                              void* d_out, int out_size) {
    (void)in_sizes; (void)n_in; (void)out_size;
    const float* x        = (const float*)d_in[0];
    const float* conv0_w  = (const float*)d_in[1];
    const float* conv_w   = (const float*)d_in[2];
    // d_in[3] = conv_b: zero and exactly cancelled by BN -> unused
    const float* bn_gamma = (const float*)d_in[4];
    const float* bn_beta  = (const float*)d_in[5];
    const float* reg_w    = (const float*)d_in[6];
    const float* reg_b    = (const float*)d_in[7];
    const float* att_w    = (const float*)d_in[8];
    float* out = (float*)d_out;

    float *p_y, *p_part, *p_wT;
    cudaGetSymbolAddress((void**)&p_y, g_y);
    cudaGetSymbolAddress((void**)&p_part, g_part);
    cudaGetSymbolAddress((void**)&p_wT, g_wT);

    wtrans_kernel<<<640, 256>>>(conv0_w, conv_w, reg_w);

    // layer 0: 12 -> 64 (no BN on input), tiles of 2 rows, split-K x4
    conv2_kernel<12, 64, 2, false, 64><<<dim3(64, 4), 256>>>(x, p_wT, p_part);
    stats_kernel<<<256, 256>>>(bn_gamma + 0, bn_beta + 0, 0);

    // layers 1..4: 64 -> 64, BN+ReLU folded into input stage
    conv2_kernel<64, 64, 2, true, 64><<<dim3(64, 4), 256>>>(p_y, p_wT + 6912 + 0 * 36864, p_part);
    stats_kernel<<<256, 256>>>(bn_gamma + 1 * 64, bn_beta + 1 * 64, 1);
    conv2_kernel<64, 64, 2, true, 64><<<dim3(64, 4), 256>>>(p_y, p_wT + 6912 + 1 * 36864, p_part);
    stats_kernel<<<256, 256>>>(bn_gamma + 2 * 64, bn_beta + 2 * 64, 2);
    conv2_kernel<64, 64, 2, true, 64><<<dim3(64, 4), 256>>>(p_y, p_wT + 6912 + 2 * 36864, p_part);
    stats_kernel<<<256, 256>>>(bn_gamma + 3 * 64, bn_beta + 3 * 64, 3);
    conv2_kernel<64, 64, 2, true, 64><<<dim3(64, 4), 256>>>(p_y, p_wT + 6912 + 3 * 36864, p_part);
    stats_kernel<<<256, 256>>>(bn_gamma + 4 * 64, bn_beta + 4 * 64, 4);

    // regressor: 64 -> 12 (padded to 16 co), 8-row tiles, BN4+ReLU on input
    conv2_kernel<64, 16, 8, true, 12><<<dim3(16, 4), 256>>>(p_y, p_wT + 154368, p_part);
    combine_xf_kernel<<<192, 256>>>(reg_b);

    // attention: out (49152 floats) then att (4*12*1024*1024)
    attention_kernel<<<49152, 256>>>(att_w, out, out + 49152);
}

// round 3
// speedup vs baseline: 1.4942x; 1.1187x over previous
#include <cuda_runtime.h>

typedef unsigned long long ull;
#define EPSV 1e-5f
#define SLICE (4 * 64 * 1024)

// ---------------- scratch (device globals) ----------------
__device__ float g_part[8][SLICE];           // split-K(<=8) partial conv outputs
__device__ float g_y[SLICE];                 // combined raw conv output (pre-BN)
__device__ float g_bn_a[64];                 // folded BN scale
__device__ float g_bn_b[64];                 // folded BN shift
__device__ float g_xf[4 * 12 * 1024];        // regressor output (N,T,WH)
__device__ float g_wT[163584];               // transposed weights [ci][tap][co]
__device__ float2 g_red[64][4];              // per-(channel, image) {sum, sumsq}
__device__ int g_cnt[5 * 64];                // last-block counters per layer/channel

// wT layout: L0 [12][9][64] @0 (6912); L1..4 [64][9][64] @6912+l*36864; reg [64][9][16] @154368

__device__ __forceinline__ void fma2(ull& acc, ull x, ull w) {
    asm("fma.rn.f32x2 %0, %1, %2, %0;" : "+l"(acc) : "l"(x), "l"(w));
}

// ---------------- weight transpose + counter reset ----------------
__global__ void wtrans_kernel(const float* __restrict__ conv0_w,
                              const float* __restrict__ conv_w,
                              const float* __restrict__ reg_w) {
    int i = blockIdx.x * 256 + threadIdx.x;
    if (i < 320) g_cnt[i] = 0;
    if (i < 6912) {
        int co = i & 63, rest = i >> 6;
        int tap = rest % 9, ci = rest / 9;
        g_wT[i] = conv0_w[co * 108 + ci * 9 + tap];
        return;
    }
    int j = i - 6912;
    if (j >= 0 && j < 147456) {
        int l = j / 36864, k = j % 36864;
        int co = k & 63, rest = k >> 6;
        int tap = rest % 9, ci = rest / 9;
        g_wT[i] = conv_w[(l * 64 + co) * 576 + ci * 9 + tap];
        return;
    }
    int r = i - 154368;
    if (r >= 0 && r < 9216) {
        int co = r & 15, rest = r >> 4;
        int tap = rest % 9, ci = rest / 9;
        g_wT[i] = (co < 12) ? reg_w[co * 576 + ci * 9 + tap] : 0.f;
    }
}

// ---------------- conv3x3 SAME, split-K, packed f32x2 FMA, single-stage ----------------
// in:  [4][CI][32][32] raw; if BN: relu(a*v+b) applied on SMEM stage
// wT:  [CI][9][CO]; part slice blockIdx.y: layout [n][STORECO][1024]
template <int CI, int CO, int ROWS, bool BN, int STORECO, int SPLITK>
__global__ __launch_bounds__(256) void conv3_kernel(const float* __restrict__ in,
                                                    const float* __restrict__ wT,
                                                    float* __restrict__ part) {
    constexpr int TCO = CO / 4;               // co-quads per row of threads
    constexpr int CIQ = CI / SPLITK;          // ci handled by this block
    const int tid = threadIdx.x;
    const int tco = tid % TCO;
    const int tpx = tid / TCO;                // px-quad index
    const int pr = tpx >> 3;                  // row within tile
    const int pc = (tpx & 7) * 4;             // col base
    const int px0 = blockIdx.x * (ROWS * 32);
    const int n = px0 >> 10;
    const int r0 = (px0 & 1023) >> 5;
    const int ci0 = blockIdx.y * CIQ;

    __shared__ __align__(16) float2 smA[CIQ][ROWS + 2][36];  // duplicated pixels
    __shared__ __align__(16) float smW[CIQ][9][CO];

    // ---- single-shot staging ----
    for (int idx = tid; idx < CIQ * (ROWS + 2) * 36; idx += 256) {
        int ci = idx / ((ROWS + 2) * 36);
        int rem = idx % ((ROWS + 2) * 36);
        int row = rem / 36, col = rem % 36;
        int gr = r0 - 1 + row, gc = col - 1;
        int cig = ci0 + ci;
        float v = 0.f;
        if ((unsigned)gr < 32u && (unsigned)gc < 32u) {
            v = in[((n * CI + cig) << 10) + (gr << 5) + gc];
            if (BN) v = fmaxf(fmaf(v, g_bn_a[cig], g_bn_b[cig]), 0.f);
        }
        smA[ci][row][col] = make_float2(v, v);
    }
    {
        const float4* src = (const float4*)(wT + ci0 * 9 * CO);
        float4* dstw = (float4*)&smW[0][0][0];
        for (int idx = tid; idx < CIQ * 9 * CO / 4; idx += 256) dstw[idx] = src[idx];
    }
    __syncthreads();

    // ---- compute: fully unrolled, no further barriers ----
    ull acc[4][2];
#pragma unroll
    for (int a = 0; a < 4; a++) { acc[a][0] = 0ULL; acc[a][1] = 0ULL; }

#pragma unroll
    for (int ci = 0; ci < CIQ; ci++) {
#pragma unroll
        for (int kh = 0; kh < 3; kh++) {
            ull xp[6];
#pragma unroll
            for (int j = 0; j < 6; j++) xp[j] = *(const ull*)&smA[ci][pr + kh][pc + j];
#pragma unroll
            for (int kw = 0; kw < 3; kw++) {
                ulonglong2 wv = *(const ulonglong2*)&smW[ci][kh * 3 + kw][tco * 4];
#pragma unroll
                for (int jp = 0; jp < 4; jp++) {
                    fma2(acc[jp][0], xp[kw + jp], wv.x);
                    fma2(acc[jp][1], xp[kw + jp], wv.y);
                }
            }
        }
    }

    // ---- epilogue ----
    union U { ull u; float2 f; };
    float vals[4][4];
#pragma unroll
    for (int jp = 0; jp < 4; jp++) {
        U u0, u1; u0.u = acc[jp][0]; u1.u = acc[jp][1];
        vals[jp][0] = u0.f.x; vals[jp][1] = u0.f.y;
        vals[jp][2] = u1.f.x; vals[jp][3] = u1.f.y;
    }
    float* dst = part + blockIdx.y * SLICE;
#pragma unroll
    for (int jc = 0; jc < 4; jc++) {
        int co = tco * 4 + jc;
        if (STORECO == CO || co < STORECO) {
            float4 o = make_float4(vals[0][jc], vals[1][jc], vals[2][jc], vals[3][jc]);
            *(float4*)&dst[((n * STORECO + co) << 10) + ((r0 + pr) << 5) + pc] = o;
        }
    }
}

// ---------------- combine partials -> y, BN stats, last-block folds (a,b) ----------------
template <int NPARTS>
__global__ __launch_bounds__(256) void stats_kernel(const float* __restrict__ gamma,
                                                    const float* __restrict__ beta,
                                                    int layer) {
    const int b = blockIdx.x;
    const int c = b & 63;        // channel
    const int n = b >> 6;        // image
    const int tid = threadIdx.x;
    const int base = ((n * 64 + c) << 10) + tid * 4;

    float4 y = make_float4(0.f, 0.f, 0.f, 0.f);
#pragma unroll
    for (int p = 0; p < NPARTS; p++) {
        float4 v = *(const float4*)&g_part[p][base];
        y.x += v.x; y.y += v.y; y.z += v.z; y.w += v.w;
    }
    *(float4*)&g_y[base] = y;
    float s = y.x + y.y + y.z + y.w;
    float ss = y.x * y.x + y.y * y.y + y.z * y.z + y.w * y.w;

    const int lane = tid & 31, warp = tid >> 5;
#pragma unroll
    for (int o = 16; o > 0; o >>= 1) {
        s += __shfl_xor_sync(0xffffffffu, s, o);
        ss += __shfl_xor_sync(0xffffffffu, ss, o);
    }
    __shared__ float shs[8], shq[8];
    if (lane == 0) { shs[warp] = s; shq[warp] = ss; }
    __syncthreads();
    if (tid == 0) {
        float S = 0.f, Q = 0.f;
#pragma unroll
        for (int k = 0; k < 8; k++) { S += shs[k]; Q += shq[k]; }
        g_red[c][n] = make_float2(S, Q);
        __threadfence();
        int old = atomicAdd(&g_cnt[layer * 64 + c], 1);
        if (old == 3) {
            __threadfence();
            volatile float* rp = (volatile float*)&g_red[c][0];
            float TS = 0.f, TQ = 0.f;
#pragma unroll
            for (int k = 0; k < 4; k++) { TS += rp[2 * k]; TQ += rp[2 * k + 1]; }
            float mean = TS * (1.f / 4096.f);
            float var = TQ * (1.f / 4096.f) - mean * mean;
            float a = gamma[c] * rsqrtf(var + EPSV);
            g_bn_a[c] = a;
            g_bn_b[c] = beta[c] - mean * a;
        }
    }
}

// ---------------- combine regressor partials + bias -> xf ----------------
__global__ void combine_xf_kernel(const float* __restrict__ reg_b) {
    int i = blockIdx.x * 256 + threadIdx.x;
    if (i < 4 * 12 * 1024) {
        int c = (i >> 10) % 12;
        float s = reg_b[c];
#pragma unroll
        for (int p = 0; p < 8; p++) s += g_part[p][i];
        g_xf[i] = s;
    }
}

// ---------------- attention: block per (t,i), loop over n ----------------
__global__ __launch_bounds__(256) void attention_kernel(const float* __restrict__ att_w,
                                                        float* __restrict__ out,
                                                        float* __restrict__ att) {
    const int ti = blockIdx.x;           // t*1024 + i
    const int t = ti >> 10;
    const int tid = threadIdx.x;
    const int lane = tid & 31, warp = tid >> 5;

    const float4 w = __ldg(((const float4*)(att_w + ((size_t)ti << 10))) + tid);
    __shared__ float shA[8], shS[8], shD[8];

#pragma unroll 1
    for (int n = 0; n < 4; n++) {
        const int nt = n * 12 + t;
        float4 x = __ldg(((const float4*)(g_xf + ((size_t)nt << 10))) + tid);
        float s0 = w.x * x.x, s1 = w.y * x.y, s2 = w.z * x.z, s3 = w.w * x.w;

        float m = fmaxf(fmaxf(s0, s1), fmaxf(s2, s3));
#pragma unroll
        for (int o = 16; o > 0; o >>= 1) m = fmaxf(m, __shfl_xor_sync(0xffffffffu, m, o));
        if (lane == 0) shA[warp] = m;
        __syncthreads();
        m = shA[0];
#pragma unroll
        for (int k = 1; k < 8; k++) m = fmaxf(m, shA[k]);

        float e0 = __expf(s0 - m), e1 = __expf(s1 - m), e2 = __expf(s2 - m), e3 = __expf(s3 - m);
        float es = e0 + e1 + e2 + e3;
        float ed = e0 * x.x + e1 * x.y + e2 * x.z + e3 * x.w;
#pragma unroll
        for (int o = 16; o > 0; o >>= 1) {
            es += __shfl_xor_sync(0xffffffffu, es, o);
            ed += __shfl_xor_sync(0xffffffffu, ed, o);
        }
        if (lane == 0) { shS[warp] = es; shD[warp] = ed; }
        __syncthreads();
        float tes = shS[0], ted = shD[0];
#pragma unroll
        for (int k = 1; k < 8; k++) { tes += shS[k]; ted += shD[k]; }

        float inv = __frcp_rn(tes);
        float4 o4 = make_float4(e0 * inv, e1 * inv, e2 * inv, e3 * inv);
        const size_t rid = ((size_t)nt << 10) + (ti & 1023);
        __stcs(((float4*)(att + (rid << 10))) + tid, o4);
        if (tid == 0) out[rid] = ted * inv;
    }
}

// ---------------- launcher ----------------
extern "C" void kernel_launch(void* const* d_in, const int* in_sizes, int n_in,
                              void* d_out, int out_size) {
    (void)in_sizes; (void)n_in; (void)out_size;
    const float* x        = (const float*)d_in[0];
    const float* conv0_w  = (const float*)d_in[1];
    const float* conv_w   = (const float*)d_in[2];
    // d_in[3] = conv_b: zero and exactly cancelled by BN -> unused
    const float* bn_gamma = (const float*)d_in[4];
    const float* bn_beta  = (const float*)d_in[5];
    const float* reg_w    = (const float*)d_in[6];
    const float* reg_b    = (const float*)d_in[7];
    const float* att_w    = (const float*)d_in[8];
    float* out = (float*)d_out;

    float *p_y, *p_part, *p_wT;
    cudaGetSymbolAddress((void**)&p_y, g_y);
    cudaGetSymbolAddress((void**)&p_part, g_part);
    cudaGetSymbolAddress((void**)&p_wT, g_wT);

    wtrans_kernel<<<640, 256>>>(conv0_w, conv_w, reg_w);

    // layer 0: 12 -> 64 (no BN on input), split-K x4 (CIQ=3)
    conv3_kernel<12, 64, 2, false, 64, 4><<<dim3(64, 4), 256>>>(x, p_wT, p_part);
    stats_kernel<4><<<256, 256>>>(bn_gamma + 0, bn_beta + 0, 0);

    // layers 1..4: 64 -> 64, split-K x8 (CIQ=8), BN+ReLU folded into input stage
    conv3_kernel<64, 64, 2, true, 64, 8><<<dim3(64, 8), 256>>>(p_y, p_wT + 6912 + 0 * 36864, p_part);
    stats_kernel<8><<<256, 256>>>(bn_gamma + 1 * 64, bn_beta + 1 * 64, 1);
    conv3_kernel<64, 64, 2, true, 64, 8><<<dim3(64, 8), 256>>>(p_y, p_wT + 6912 + 1 * 36864, p_part);
    stats_kernel<8><<<256, 256>>>(bn_gamma + 2 * 64, bn_beta + 2 * 64, 2);
    conv3_kernel<64, 64, 2, true, 64, 8><<<dim3(64, 8), 256>>>(p_y, p_wT + 6912 + 2 * 36864, p_part);
    stats_kernel<8><<<256, 256>>>(bn_gamma + 3 * 64, bn_beta + 3 * 64, 3);
    conv3_kernel<64, 64, 2, true, 64, 8><<<dim3(64, 8), 256>>>(p_y, p_wT + 6912 + 3 * 36864, p_part);
    stats_kernel<8><<<256, 256>>>(bn_gamma + 4 * 64, bn_beta + 4 * 64, 4);

    // regressor: 64 -> 12 (padded to 16 co), 8-row tiles, split-K x8
    conv3_kernel<64, 16, 8, true, 12, 8><<<dim3(16, 8), 256>>>(p_y, p_wT + 154368, p_part);
    combine_xf_kernel<<<192, 256>>>(reg_b);

    // attention: out (49152 floats) then att (4*12*1024*1024)
    attention_kernel<<<12288, 256>>>(att_w, out, out + 49152);
}